// round 1
// baseline (speedup 1.0000x reference)
#include <cuda_runtime.h>

#define BATCH  8
#define SEQ    512
#define NHEAD  8
#define HDIM   64
#define DMODEL 512
#define NREL   1023
#define ZOFF   511

// Scratch (allocation-free rule: __device__ globals)
__device__ float g_Q[BATCH*NHEAD*SEQ*HDIM];
__device__ float g_K[BATCH*NHEAD*SEQ*HDIM];
__device__ float g_V[BATCH*NHEAD*SEQ*HDIM];
__device__ float g_ctx[BATCH*SEQ*DMODEL];

// ---------------------------------------------------------------------------
// QKV projection: out[b,h,i,d] = sum_k X[b,i,k]*W[k,h*64+d] + bias
// M=4096, N=512, K=512.  64x64 tile, BK=16, 256 threads, 4x4 per thread.
// ---------------------------------------------------------------------------
__global__ void __launch_bounds__(256) qkv_gemm_kernel(
    const float* __restrict__ X,
    const float* __restrict__ Wq, const float* __restrict__ bq,
    const float* __restrict__ Wk, const float* __restrict__ bk,
    const float* __restrict__ Wv, const float* __restrict__ bv)
{
    const int z = blockIdx.z;
    const float* __restrict__ W    = (z==0) ? Wq : (z==1) ? Wk : Wv;
    const float* __restrict__ bias = (z==0) ? bq : (z==1) ? bk : bv;
    float* out = (z==0) ? g_Q : (z==1) ? g_K : g_V;

    __shared__ float As[16][68];   // [k][m], pad 68 keeps 16B alignment
    __shared__ float Bs[16][64];   // [k][n]

    const int m0 = blockIdx.y * 64;
    const int n0 = blockIdx.x * 64;
    const int tid = threadIdx.x;
    const int tx = tid & 15;
    const int ty = tid >> 4;

    float acc[4][4];
    #pragma unroll
    for (int u = 0; u < 4; u++)
        #pragma unroll
        for (int v = 0; v < 4; v++) acc[u][v] = 0.f;

    for (int k0 = 0; k0 < DMODEL; k0 += 16) {
        #pragma unroll
        for (int t = tid; t < 1024; t += 256) {
            int mm = t >> 4, kk = t & 15;
            As[kk][mm] = X[(m0+mm)*DMODEL + k0+kk];
        }
        #pragma unroll
        for (int t = tid; t < 1024; t += 256) {
            int kk = t >> 6, nn = t & 63;
            Bs[kk][nn] = W[(k0+kk)*DMODEL + n0+nn];
        }
        __syncthreads();
        #pragma unroll
        for (int kk = 0; kk < 16; kk++) {
            float4 a = *(const float4*)&As[kk][ty*4];
            float4 w = *(const float4*)&Bs[kk][tx*4];
            acc[0][0]+=a.x*w.x; acc[0][1]+=a.x*w.y; acc[0][2]+=a.x*w.z; acc[0][3]+=a.x*w.w;
            acc[1][0]+=a.y*w.x; acc[1][1]+=a.y*w.y; acc[1][2]+=a.y*w.z; acc[1][3]+=a.y*w.w;
            acc[2][0]+=a.z*w.x; acc[2][1]+=a.z*w.y; acc[2][2]+=a.z*w.z; acc[2][3]+=a.z*w.w;
            acc[3][0]+=a.w*w.x; acc[3][1]+=a.w*w.y; acc[3][2]+=a.w*w.z; acc[3][3]+=a.w*w.w;
        }
        __syncthreads();
    }
    #pragma unroll
    for (int u = 0; u < 4; u++) {
        int m = m0 + ty*4 + u;
        int bb = m >> 9, ii = m & 511;
        #pragma unroll
        for (int v = 0; v < 4; v++) {
            int n = n0 + tx*4 + v;
            int hh = n >> 6, dd = n & 63;
            out[(((bb*NHEAD + hh)*SEQ) + ii)*HDIM + dd] = acc[u][v] + bias[n];
        }
    }
}

// ---------------------------------------------------------------------------
// Output projection: d_out = g_ctx[4096,512] @ Wo[512,512] + bo
// ---------------------------------------------------------------------------
__global__ void __launch_bounds__(256) out_gemm_kernel(
    const float* __restrict__ Wo, const float* __restrict__ bo,
    float* __restrict__ out)
{
    __shared__ float As[16][68];
    __shared__ float Bs[16][64];

    const int m0 = blockIdx.y * 64;
    const int n0 = blockIdx.x * 64;
    const int tid = threadIdx.x;
    const int tx = tid & 15;
    const int ty = tid >> 4;

    float acc[4][4];
    #pragma unroll
    for (int u = 0; u < 4; u++)
        #pragma unroll
        for (int v = 0; v < 4; v++) acc[u][v] = 0.f;

    for (int k0 = 0; k0 < DMODEL; k0 += 16) {
        #pragma unroll
        for (int t = tid; t < 1024; t += 256) {
            int mm = t >> 4, kk = t & 15;
            As[kk][mm] = g_ctx[(m0+mm)*DMODEL + k0+kk];
        }
        #pragma unroll
        for (int t = tid; t < 1024; t += 256) {
            int kk = t >> 6, nn = t & 63;
            Bs[kk][nn] = Wo[(k0+kk)*DMODEL + n0+nn];
        }
        __syncthreads();
        #pragma unroll
        for (int kk = 0; kk < 16; kk++) {
            float4 a = *(const float4*)&As[kk][ty*4];
            float4 w = *(const float4*)&Bs[kk][tx*4];
            acc[0][0]+=a.x*w.x; acc[0][1]+=a.x*w.y; acc[0][2]+=a.x*w.z; acc[0][3]+=a.x*w.w;
            acc[1][0]+=a.y*w.x; acc[1][1]+=a.y*w.y; acc[1][2]+=a.y*w.z; acc[1][3]+=a.y*w.w;
            acc[2][0]+=a.z*w.x; acc[2][1]+=a.z*w.y; acc[2][2]+=a.z*w.z; acc[2][3]+=a.z*w.w;
            acc[3][0]+=a.w*w.x; acc[3][1]+=a.w*w.y; acc[3][2]+=a.w*w.z; acc[3][3]+=a.w*w.w;
        }
        __syncthreads();
    }
    #pragma unroll
    for (int u = 0; u < 4; u++) {
        int m = m0 + ty*4 + u;
        #pragma unroll
        for (int v = 0; v < 4; v++) {
            int n = n0 + tx*4 + v;
            out[m*DMODEL + n] = acc[u][v] + bo[n];
        }
    }
}

// ---------------------------------------------------------------------------
// Fused attention with relative positional embeddings.
// Block = 256 threads, handles one (b, h, 32-query tile). Flash-style online
// softmax over 8 key-chunks of 64. Relative-V trick: for tile (i0..i0+31,
// j0..j0+63) the needed P_v rows are the 95 contiguous rows starting at
// ZOFF + j0 - i0 - 31 of P_v[:,h,:].
// ---------------------------------------------------------------------------
#define SMF_QS   0                      // Qs[64][36]  (Q transposed [d][il])
#define SMF_KS   (SMF_QS + 64*36)       // Ks[64][132] (K transposed [d][j])
#define SMF_VS   (SMF_KS + 64*132)      // Vs[64][64]  ([j][d])
#define SMF_PVS  (SMF_VS + 64*64)       // Pvs[96][64] ([r][d])
#define SMF_SC   (SMF_PVS + 96*64)      // Sc[32][64]  (scores/probs)
#define SMF_M    (SMF_SC + 32*64)       // m[32]
#define SMF_S    (SMF_M + 32)           // sum[32]
#define SMF_F    (SMF_S + 32)           // rescale factor[32]
#define SMF_TOTAL (SMF_F + 32)          // floats
#define ATTN_SMEM_BYTES (SMF_TOTAL * 4)

__global__ void __launch_bounds__(256) attn_kernel(
    const float* __restrict__ Pk, const float* __restrict__ Pv)
{
    extern __shared__ float sm[];
    float* Qs  = sm + SMF_QS;
    float* Ks  = sm + SMF_KS;
    float* Vs  = sm + SMF_VS;
    float* Pvs = sm + SMF_PVS;
    float* Sc  = sm + SMF_SC;
    float* mrow = sm + SMF_M;
    float* srow = sm + SMF_S;
    float* frow = sm + SMF_F;

    const int i0  = blockIdx.x * 32;
    const int h   = blockIdx.y;
    const int b   = blockIdx.z;
    const int tid = threadIdx.x;

    const float* Qg = g_Q + (size_t)((b*NHEAD + h)*SEQ) * HDIM;
    const float* Kg = g_K + (size_t)((b*NHEAD + h)*SEQ) * HDIM;
    const float* Vg = g_V + (size_t)((b*NHEAD + h)*SEQ) * HDIM;

    // Load Q tile transposed: Qs[d][il]
    for (int idx = tid; idx < 32*64; idx += 256) {
        int dd = idx & 63, il = idx >> 6;
        Qs[dd*36 + il] = Qg[(i0+il)*HDIM + dd];
    }
    if (tid < 32) { mrow[tid] = -1e30f; srow[tid] = 0.f; }

    float acc[8];
    #pragma unroll
    for (int q = 0; q < 8; q++) acc[q] = 0.f;

    const int ti = tid >> 4;    // 0..15: query pair base = ti*2
    const int tj = tid & 15;    // 0..15: key quad base  = tj*4
    const int qg = tid >> 6;    // 0..3 : query group for accumulate
    const int d  = tid & 63;    // value dim for accumulate
    const float scale = 0.125f; // 1/sqrt(64)

    for (int jc = 0; jc < 8; jc++) {
        const int j0 = jc * 64;
        __syncthreads();  // previous chunk consumers done before overwrite

        // Stage K (transposed), V, and the P_v diagonal band
        for (int idx = tid; idx < 64*64; idx += 256) {
            int dd = idx & 63, j = idx >> 6;
            Ks[dd*132 + j] = Kg[(j0+j)*HDIM + dd];
            Vs[j*64 + dd]  = Vg[(j0+j)*HDIM + dd];
        }
        const int rbase = ZOFF + j0 - i0 - 31;  // rows rbase..rbase+94 used
        for (int idx = tid; idx < 96*64; idx += 256) {
            int dd = idx & 63, r = idx >> 6;
            int rr = rbase + r;
            rr = (rr < 0) ? 0 : (rr > NREL-1) ? NREL-1 : rr;  // row 95 pad only
            Pvs[r*64 + dd] = Pv[((size_t)rr*NHEAD + h)*HDIM + dd];
        }
        __syncthreads();

        // Scores: each thread 2 queries x 4 keys
        {
            const int il0 = ti*2;
            const int jl0 = tj*4;
            float s00=0.f,s01=0.f,s02=0.f,s03=0.f;
            float s10=0.f,s11=0.f,s12=0.f,s13=0.f;
            #pragma unroll 16
            for (int kk = 0; kk < 64; kk++) {
                float a0 = Qs[kk*36 + il0];
                float a1 = Qs[kk*36 + il0 + 1];
                float4 kb = *(const float4*)&Ks[kk*132 + jl0];
                s00 += a0*kb.x; s01 += a0*kb.y; s02 += a0*kb.z; s03 += a0*kb.w;
                s10 += a1*kb.x; s11 += a1*kb.y; s12 += a1*kb.z; s13 += a1*kb.w;
            }
            int i = i0 + il0;
            int relb = ZOFF + j0 + jl0 - i;   // in [0,1022] always
            float4 o;
            o.x = (s00 + Pk[(relb+0)*NHEAD + h]) * scale;
            o.y = (s01 + Pk[(relb+1)*NHEAD + h]) * scale;
            o.z = (s02 + Pk[(relb+2)*NHEAD + h]) * scale;
            o.w = (s03 + Pk[(relb+3)*NHEAD + h]) * scale;
            *(float4*)&Sc[il0*64 + jl0] = o;
            relb -= 1;  // query i+1
            o.x = (s10 + Pk[(relb+0)*NHEAD + h]) * scale;
            o.y = (s11 + Pk[(relb+1)*NHEAD + h]) * scale;
            o.z = (s12 + Pk[(relb+2)*NHEAD + h]) * scale;
            o.w = (s13 + Pk[(relb+3)*NHEAD + h]) * scale;
            *(float4*)&Sc[(il0+1)*64 + jl0] = o;
        }
        __syncthreads();

        // Online softmax update: warp w owns rows w*4..w*4+3
        {
            const int w = tid >> 5, lane = tid & 31;
            #pragma unroll
            for (int r = 0; r < 4; r++) {
                int il = w*4 + r;
                float v0 = Sc[il*64 + lane];
                float v1 = Sc[il*64 + 32 + lane];
                float cm = fmaxf(v0, v1);
                #pragma unroll
                for (int o = 16; o > 0; o >>= 1)
                    cm = fmaxf(cm, __shfl_xor_sync(0xffffffffu, cm, o));
                float mold = mrow[il];
                float mnew = fmaxf(mold, cm);
                float e0 = __expf(v0 - mnew);
                float e1 = __expf(v1 - mnew);
                Sc[il*64 + lane]      = e0;
                Sc[il*64 + 32 + lane] = e1;
                float es = e0 + e1;
                #pragma unroll
                for (int o = 16; o > 0; o >>= 1)
                    es += __shfl_xor_sync(0xffffffffu, es, o);
                if (lane == 0) {
                    float f = __expf(mold - mnew);
                    frow[il] = f;
                    srow[il] = srow[il] * f + es;
                    mrow[il] = mnew;
                }
            }
        }
        __syncthreads();

        // Accumulate: thread = (qg: 8 queries, d).  Sliding-window P_v rows:
        // row(jj, q) = jj + 31 - il(q), il(q) = qg*8 + q; advancing jj by 1
        // shifts the 8-row window by 1 -> 1 fresh LDS per jj.
        {
            #pragma unroll
            for (int q = 0; q < 8; q++) acc[q] *= frow[qg*8 + q];
            float pv[8];
            #pragma unroll
            for (int q = 0; q < 8; q++)
                pv[q] = Pvs[(31 - (qg*8 + q))*64 + d];
            #pragma unroll 8
            for (int jj = 0; jj < 64; jj++) {
                float v = Vs[jj*64 + d];
                #pragma unroll
                for (int q = 0; q < 8; q++) {
                    float p = Sc[(qg*8 + q)*64 + jj];
                    acc[q] += p * (v + pv[q]);
                }
                #pragma unroll
                for (int q = 7; q > 0; q--) pv[q] = pv[q-1];
                pv[0] = Pvs[(jj + 32 - qg*8)*64 + d];  // row <= 95, staged
            }
        }
    }

    // Final: normalize and write context [b, i, h*64+d]
    #pragma unroll
    for (int q = 0; q < 8; q++) {
        int il = qg*8 + q;
        g_ctx[((size_t)(b*SEQ + i0 + il))*DMODEL + h*HDIM + d] = acc[q] / srow[il];
    }
}

// ---------------------------------------------------------------------------
extern "C" void kernel_launch(void* const* d_in, const int* in_sizes, int n_in,
                              void* d_out, int out_size)
{
    const float* X  = (const float*)d_in[0];
    const float* Wq = (const float*)d_in[1];
    const float* bq = (const float*)d_in[2];
    const float* Wk = (const float*)d_in[3];
    const float* bk = (const float*)d_in[4];
    const float* Wv = (const float*)d_in[5];
    const float* bv = (const float*)d_in[6];
    const float* Wo = (const float*)d_in[7];
    const float* bo = (const float*)d_in[8];
    const float* Pk = (const float*)d_in[9];
    const float* Pv = (const float*)d_in[10];
    float* out = (float*)d_out;

    cudaFuncSetAttribute(attn_kernel,
                         cudaFuncAttributeMaxDynamicSharedMemorySize,
                         ATTN_SMEM_BYTES);

    // 1) Q/K/V projections (z selects which)
    qkv_gemm_kernel<<<dim3(8, 64, 3), 256>>>(X, Wq, bq, Wk, bk, Wv, bv);

    // 2) Fused attention (+ relative K bias, + relative V mixing)
    attn_kernel<<<dim3(16, NHEAD, BATCH), 256, ATTN_SMEM_BYTES>>>(Pk, Pv);

    // 3) Output projection
    out_gemm_kernel<<<dim3(8, 64), 256>>>(Wo, bo, out);
}